// round 10
// baseline (speedup 1.0000x reference)
#include <cuda_runtime.h>
#include <cuda_bf16.h>

// Problem constants
#define PB   32
#define PT   8192
#define PC   3
#define PLS  32
#define PNS  256
#define PW   (PT - PLS + 1)        // 8161

#define KF      96                 // K = LS*C
#define NTILE   64                 // windows per item
#define WTILES  (PT / NTILE)       // 128
#define NITEMS  (PB * WTILES)      // 4096
#define THREADS 256

#define FLATN   (PT * PC)          // 24576
#define PTF     (FLATN + 96)       // phase-array padded length (24672)

#define BSTR    208                // B row stride bytes (104 bf16, conflict-free)
#define BTERM   13312              // 64 rows * 208
#define BUFSZ   26624              // hi + lo
#define SM_A2   53248              // 2 x 64 floats
#define SM_TOT  53760

typedef unsigned int u32;
typedef unsigned short u16;
typedef unsigned long long u64;

// Device scratch (allocations forbidden)
__device__ __align__(16) u16 g_xhi[8 * PB * PTF];   // 8 phase-shifted flat bf16 hi
__device__ __align__(16) u16 g_xlo[8 * PB * PTF];   // 8 phase-shifted flat bf16 lo
__device__ float g_d2[PB * PT];
__device__ float g_a2[PB * PT];                     // padded; >=PW poisoned
__device__ float g_k2[PNS];
__device__ u32   g_amin[PB * PNS];
__device__ u32   g_done;

// ---------------------------------------------------------------------------
__device__ __forceinline__ u32 smem_u32(const void* p) {
    u32 a; asm("{ .reg .u64 t; cvta.to.shared.u64 t, %1; cvt.u32.u64 %0, t; }"
               : "=r"(a) : "l"(p));
    return a;
}
__device__ __forceinline__ u32 fenc(float f) {
    u32 u = __float_as_uint(f);
    return (u & 0x80000000u) ? ~u : (u | 0x80000000u);
}
__device__ __forceinline__ float fdec(u32 u) {
    u32 b = (u & 0x80000000u) ? (u & 0x7FFFFFFFu) : ~u;
    return __uint_as_float(b);
}
// split float into bf16 hi/lo, pack two splits into u32s
__device__ __forceinline__ void split2(float v0, float v1, u32& hi, u32& lo) {
    __nv_bfloat16 h0 = __float2bfloat16(v0);
    __nv_bfloat16 h1 = __float2bfloat16(v1);
    __nv_bfloat16 l0 = __float2bfloat16(v0 - __bfloat162float(h0));
    __nv_bfloat16 l1 = __float2bfloat16(v1 - __bfloat162float(h1));
    hi = (u32)__bfloat16_as_ushort(h0) | ((u32)__bfloat16_as_ushort(h1) << 16);
    lo = (u32)__bfloat16_as_ushort(l0) | ((u32)__bfloat16_as_ushort(l1) << 16);
}

#define LDSM4(r0, r1, r2, r3, addr) \
    asm volatile("ldmatrix.sync.aligned.m8n8.x4.shared.b16 {%0,%1,%2,%3}, [%4];" \
        : "=r"(r0), "=r"(r1), "=r"(r2), "=r"(r3) : "r"(addr))

#define MMA16816(d, a0, a1, a2, a3, b0, b1) \
    asm volatile("mma.sync.aligned.m16n8k16.row.col.f32.bf16.bf16.f32 " \
        "{%0,%1,%2,%3}, {%4,%5,%6,%7}, {%8,%9}, {%0,%1,%2,%3};" \
        : "+f"((d)[0]), "+f"((d)[1]), "+f"((d)[2]), "+f"((d)[3]) \
        : "r"(a0), "r"(a1), "r"(a2), "r"(a3), "r"(b0), "r"(b1))

#define CPASYNC16(dst, src) \
    asm volatile("cp.async.cg.shared.global [%0], [%1], 16;" :: "r"(dst), "l"(src))
#define CPASYNC4(dst, src) \
    asm volatile("cp.async.ca.shared.global [%0], [%1], 4;" :: "r"(dst), "l"(src))

// ---------------------------------------------------------------------------
// prep1: d2, amin init, k2, done counter
__global__ void prep1_kernel(const float* __restrict__ data,
                             const float* __restrict__ ker) {
    int i = blockIdx.x * blockDim.x + threadIdx.x;
    if (i < PB * PT) {
        const float* p = data + (size_t)i * 3;
        float x0 = p[0], x1 = p[1], x2 = p[2];
        g_d2[i] = x0 * x0 + x1 * x1 + x2 * x2;
    }
    if (i < PB * PNS) g_amin[i] = 0xFFFFFFFFu;
    if (i < PNS) {
        float k2 = 0.f;
        const float* kp = ker + i * KF;
        #pragma unroll 8
        for (int j = 0; j < KF; j++) { float v = kp[j]; k2 += v * v; }
        g_k2[i] = k2;
    }
    if (i == 0) g_done = 0u;
}

// prep2: phase arrays (bf16 split inline, direct from data) + a2 from d2
__global__ void prep2_kernel(const float* __restrict__ data) {
    const int HP = PTF / 2;
    int j = blockIdx.x * blockDim.x + threadIdx.x;
    if (j < 8 * PB * HP) {
        int i2 = j % HP;
        int r  = j / HP;            // = p*PB + b
        int b  = r % PB;
        int p  = r / PB;
        int e0 = 2 * i2 + p;
        const float* db = data + (size_t)b * FLATN;
        float v0 = (e0 < FLATN)     ? db[e0]     : 0.f;
        float v1 = (e0 + 1 < FLATN) ? db[e0 + 1] : 0.f;
        u32 hi, lo; split2(v0, v1, hi, lo);
        ((u32*)g_xhi)[r * HP + i2] = hi;
        ((u32*)g_xlo)[r * HP + i2] = lo;
    }
    if (j < PB * PT) {
        int b = j / PT, w = j % PT;
        float s = 1e30f;
        if (w < PW) {
            const float* d = g_d2 + b * PT + w;
            s = 0.f;
            #pragma unroll
            for (int q = 0; q < PLS; q++) s += d[q];
        }
        g_a2[j] = s;
    }
}

// ---------------------------------------------------------------------------
// issue cp.async group for one item: 2 terms x 64 rows x 12 quads + a2
__device__ __forceinline__ void issue_item(u32 sbase, int buf, int b, int w0) {
    int tid = threadIdx.x;
    u32 bufbase = sbase + (u32)buf * BUFSZ;
    #pragma unroll
    for (int rep = 0; rep < 6; rep++) {
        int c = tid + rep * 256;            // 0..1535
        int term = c / 768;
        int cc = c - term * 768;
        int row = cc / 12, q = cc - row * 12;
        int E = 3 * (w0 + row), p = E & 7;
        const u16* src = (term ? g_xlo : g_xhi)
                         + (size_t)(p * PB + b) * PTF + (E - p) + q * 8;
        u32 dst = bufbase + (u32)term * BTERM + (u32)row * BSTR + (u32)q * 16;
        CPASYNC16(dst, src);
    }
    if (tid < NTILE) {
        const float* src = g_a2 + (size_t)b * PT + w0 + tid;
        u32 dst = sbase + SM_A2 + (u32)buf * 256 + (u32)tid * 4;
        CPASYNC4(dst, src);
    }
    asm volatile("cp.async.commit_group;" ::: "memory");
}

// ---------------------------------------------------------------------------
// Main: M=256/CTA, persistent A frags (direct from ker), pipelined B LDSM.
__global__ __launch_bounds__(THREADS, 1) void mma_main_kernel(
        const float* __restrict__ ker, float* __restrict__ out) {
    extern __shared__ __align__(16) char smem[];
    u32 sbase = smem_u32(smem);
    int tid  = threadIdx.x;
    int lane = tid & 31;
    int warp = tid >> 5;                 // 0..7 -> M rows warp*32..+31
    int g    = lane >> 2;                // 0..7
    int tg   = lane & 3;                 // 0..3

    // ---- Persistent A fragments built directly from ker (-2k, hi/lo split)
    u32 Ah[48], Al[48];                  // [ks*8 + mt*4 + q]
    {
        int r0 = warp * 32 + g;
        #pragma unroll
        for (int ks = 0; ks < 6; ks++) {
            #pragma unroll
            for (int mt = 0; mt < 2; mt++) {
                int o = ks * 8 + mt * 4;
                #pragma unroll
                for (int q = 0; q < 4; q++) {
                    int row = r0 + mt * 16 + ((q & 1) ? 8 : 0);
                    int col = ks * 16 + tg * 2 + ((q & 2) ? 8 : 0);   // <= 94
                    float2 kv = *(const float2*)(ker + (size_t)row * KF + col);
                    split2(-2.f * kv.x, -2.f * kv.y, Ah[o + q], Al[o + q]);
                }
            }
        }
    }

    // ldmatrix B per-thread offset (proven mapping)
    int ti = lane >> 3, l8 = lane & 7;
    u32 boff = (u32)((((ti >> 1) * 8 + l8) * BSTR) + (ti & 1) * 16);

    // ---- prologue: prefetch first item into buf 0
    int item0 = blockIdx.x;
    issue_item(sbase, 0, item0 >> 7, (item0 & 127) * NTILE);

    int buf = 0;
    for (int u = item0; u < NITEMS; u += gridDim.x) {
        int b = u >> 7;
        int un = u + gridDim.x;
        if (un < NITEMS) {
            issue_item(sbase, buf ^ 1, un >> 7, (un & 127) * NTILE);
            asm volatile("cp.async.wait_group 1;" ::: "memory");
        } else {
            asm volatile("cp.async.wait_group 0;" ::: "memory");
        }
        __syncthreads();

        // ---- 3-term GEMM, software-pipelined B loads
        float d[2][8][4];
        #pragma unroll
        for (int mt = 0; mt < 2; mt++)
            #pragma unroll
            for (int jb = 0; jb < 8; jb++)
                #pragma unroll
                for (int q = 0; q < 4; q++) d[mt][jb][q] = 0.f;

        u32 bhbase = sbase + (u32)buf * BUFSZ + boff;
        u32 blbase = bhbase + BTERM;

        u32 bh[16], bl[16];
        #pragma unroll
        for (int jp = 0; jp < 4; jp++)
            LDSM4(bh[jp*4+0], bh[jp*4+1], bh[jp*4+2], bh[jp*4+3],
                  bhbase + jp * (16 * BSTR));

        #pragma unroll
        for (int ks = 0; ks < 6; ks++) {
            // issue bl(ks) — covered by the 32 bh-HMMAs below
            #pragma unroll
            for (int jp = 0; jp < 4; jp++)
                LDSM4(bl[jp*4+0], bl[jp*4+1], bl[jp*4+2], bl[jp*4+3],
                      blbase + jp * (16 * BSTR) + ks * 32);
            // 32 HMMA on bh: Ah*Bh + Al*Bh, both mt halves
            #pragma unroll
            for (int mt = 0; mt < 2; mt++) {
                int o = ks * 8 + mt * 4;
                #pragma unroll
                for (int jp = 0; jp < 4; jp++) {
                    MMA16816(d[mt][2*jp],   Ah[o], Ah[o+1], Ah[o+2], Ah[o+3],
                             bh[jp*4+0], bh[jp*4+1]);
                    MMA16816(d[mt][2*jp+1], Ah[o], Ah[o+1], Ah[o+2], Ah[o+3],
                             bh[jp*4+2], bh[jp*4+3]);
                    MMA16816(d[mt][2*jp],   Al[o], Al[o+1], Al[o+2], Al[o+3],
                             bh[jp*4+0], bh[jp*4+1]);
                    MMA16816(d[mt][2*jp+1], Al[o], Al[o+1], Al[o+2], Al[o+3],
                             bh[jp*4+2], bh[jp*4+3]);
                }
            }
            // issue bh(ks+1) — covered by the 16 bl-HMMAs below
            if (ks < 5) {
                #pragma unroll
                for (int jp = 0; jp < 4; jp++)
                    LDSM4(bh[jp*4+0], bh[jp*4+1], bh[jp*4+2], bh[jp*4+3],
                          bhbase + jp * (16 * BSTR) + (ks + 1) * 32);
            }
            // 16 HMMA on bl: Ah*Bl
            #pragma unroll
            for (int mt = 0; mt < 2; mt++) {
                int o = ks * 8 + mt * 4;
                #pragma unroll
                for (int jp = 0; jp < 4; jp++) {
                    MMA16816(d[mt][2*jp],   Ah[o], Ah[o+1], Ah[o+2], Ah[o+3],
                             bl[jp*4+0], bl[jp*4+1]);
                    MMA16816(d[mt][2*jp+1], Ah[o], Ah[o+1], Ah[o+2], Ah[o+3],
                             bl[jp*4+2], bl[jp*4+3]);
                }
            }
        }

        // ---- Epilogue: +a2, min over 64 windows, atomicMin per shapelet
        const float* a2sh = (const float*)(smem + SM_A2 + buf * 256);
        #pragma unroll
        for (int mt = 0; mt < 2; mt++) {
            float m0 = 3.4e38f, m1 = 3.4e38f;
            #pragma unroll
            for (int jb = 0; jb < 8; jb++) {
                float aa0 = a2sh[jb * 8 + tg * 2];
                float aa1 = a2sh[jb * 8 + tg * 2 + 1];
                m0 = fminf(m0, fminf(d[mt][jb][0] + aa0, d[mt][jb][1] + aa1));
                m1 = fminf(m1, fminf(d[mt][jb][2] + aa0, d[mt][jb][3] + aa1));
            }
            m0 = fminf(m0, __shfl_xor_sync(0xFFFFFFFFu, m0, 1));
            m0 = fminf(m0, __shfl_xor_sync(0xFFFFFFFFu, m0, 2));
            m1 = fminf(m1, __shfl_xor_sync(0xFFFFFFFFu, m1, 1));
            m1 = fminf(m1, __shfl_xor_sync(0xFFFFFFFFu, m1, 2));
            if (tg == 0) {
                int srow = warp * 32 + mt * 16 + g;
                atomicMin(&g_amin[b * PNS + srow],     fenc(m0));
                atomicMin(&g_amin[b * PNS + srow + 8], fenc(m1));
            }
        }
        __syncthreads();    // all reads of buf done before it is refilled
        buf ^= 1;
    }

    // ---- Fused finish: last CTA writes the output
    __threadfence();
    __shared__ u32 s_rank;
    if (tid == 0) s_rank = atomicAdd(&g_done, 1u);
    __syncthreads();
    if (s_rank == gridDim.x - 1) {
        __threadfence();
        for (int i = tid; i < PB * PNS; i += THREADS) {
            u32 enc = __ldcg(&g_amin[i]);
            out[i] = (fdec(enc) + g_k2[i & (PNS - 1)]) * (1.0f / (float)PLS);
        }
    }
}

// ---------------------------------------------------------------------------
extern "C" void kernel_launch(void* const* d_in, const int* in_sizes, int n_in,
                              void* d_out, int out_size) {
    const float* data = (const float*)d_in[0];   // [32, 8192, 3]
    const float* ker  = (const float*)d_in[1];   // [256, 32, 3]
    float* out = (float*)d_out;                  // [32, 256]

    cudaFuncSetAttribute(mma_main_kernel,
                         cudaFuncAttributeMaxDynamicSharedMemorySize, SM_TOT);
    int dev = 0, nsm = 148;
    cudaGetDevice(&dev);
    cudaDeviceGetAttribute(&nsm, cudaDevAttrMultiProcessorCount, dev);
    if (nsm > NITEMS) nsm = NITEMS;

    prep1_kernel<<<(PB * PT + 255) / 256, 256>>>(data, ker);
    prep2_kernel<<<(8 * PB * (PTF / 2) + 255) / 256, 256>>>(data);

    mma_main_kernel<<<nsm, THREADS, SM_TOT>>>(ker, out);
}

// round 11
// speedup vs baseline: 1.1070x; 1.1070x over previous
#include <cuda_runtime.h>
#include <cuda_bf16.h>

// Problem constants
#define PB   32
#define PT   8192
#define PC   3
#define PLS  32
#define PNS  256
#define PW   (PT - PLS + 1)        // 8161

#define KF      96                 // K = LS*C
#define KPAD    128                // global K row pad (u16 elements)
#define NTILE   64                 // windows per item
#define WTILES  (PT / NTILE)       // 128
#define NITEMS  (PB * WTILES)      // 4096
#define THREADS 256

#define FLATN   (PT * PC)          // 24576
#define PTF     (FLATN + 96)       // phase-array padded length (24672)

#define BSTR    208                // B row stride bytes (104 bf16, conflict-free)
#define BTERM   13312              // 64 rows * 208
#define BUFSZ   26624              // hi + lo
#define SM_A2   53248              // 2 x 64 floats
#define SM_TOT  53760

typedef unsigned int u32;
typedef unsigned short u16;
typedef unsigned long long u64;

// Device scratch (allocations forbidden)
__device__ __align__(16) u16 g_xhi[8 * PB * PTF];   // 8 phase-shifted flat bf16 hi
__device__ __align__(16) u16 g_xlo[8 * PB * PTF];   // 8 phase-shifted flat bf16 lo
__device__ __align__(16) u16 g_khi[PNS * KPAD];     // bf16(-2k) hi
__device__ __align__(16) u16 g_klo[PNS * KPAD];     // bf16(-2k) lo
__device__ float g_d2[PB * PT];
__device__ float g_a2[PB * PT];                     // padded; >=PW poisoned
__device__ float g_k2[PNS];
__device__ u32   g_amin[PB * PNS];
__device__ u32   g_done;

// ---------------------------------------------------------------------------
__device__ __forceinline__ u32 smem_u32(const void* p) {
    u32 a; asm("{ .reg .u64 t; cvta.to.shared.u64 t, %1; cvt.u32.u64 %0, t; }"
               : "=r"(a) : "l"(p));
    return a;
}
__device__ __forceinline__ u32 fenc(float f) {
    u32 u = __float_as_uint(f);
    return (u & 0x80000000u) ? ~u : (u | 0x80000000u);
}
__device__ __forceinline__ float fdec(u32 u) {
    u32 b = (u & 0x80000000u) ? (u & 0x7FFFFFFFu) : ~u;
    return __uint_as_float(b);
}
__device__ __forceinline__ void split2(float v0, float v1, u32& hi, u32& lo) {
    __nv_bfloat16 h0 = __float2bfloat16(v0);
    __nv_bfloat16 h1 = __float2bfloat16(v1);
    __nv_bfloat16 l0 = __float2bfloat16(v0 - __bfloat162float(h0));
    __nv_bfloat16 l1 = __float2bfloat16(v1 - __bfloat162float(h1));
    hi = (u32)__bfloat16_as_ushort(h0) | ((u32)__bfloat16_as_ushort(h1) << 16);
    lo = (u32)__bfloat16_as_ushort(l0) | ((u32)__bfloat16_as_ushort(l1) << 16);
}

#define LDSM4(r0, r1, r2, r3, addr) \
    asm volatile("ldmatrix.sync.aligned.m8n8.x4.shared.b16 {%0,%1,%2,%3}, [%4];" \
        : "=r"(r0), "=r"(r1), "=r"(r2), "=r"(r3) : "r"(addr))

#define MMA16816(d, a0, a1, a2, a3, b0, b1) \
    asm volatile("mma.sync.aligned.m16n8k16.row.col.f32.bf16.bf16.f32 " \
        "{%0,%1,%2,%3}, {%4,%5,%6,%7}, {%8,%9}, {%0,%1,%2,%3};" \
        : "+f"((d)[0]), "+f"((d)[1]), "+f"((d)[2]), "+f"((d)[3]) \
        : "r"(a0), "r"(a1), "r"(a2), "r"(a3), "r"(b0), "r"(b1))

#define CPASYNC16(dst, src) \
    asm volatile("cp.async.cg.shared.global [%0], [%1], 16;" :: "r"(dst), "l"(src))
#define CPASYNC4(dst, src) \
    asm volatile("cp.async.ca.shared.global [%0], [%1], 4;" :: "r"(dst), "l"(src))

// ---------------------------------------------------------------------------
// prep1: d2, K(-2k) hi/lo, amin init, warp-parallel k2, done counter
__global__ void prep1_kernel(const float* __restrict__ data,
                             const float* __restrict__ ker) {
    int i = blockIdx.x * blockDim.x + threadIdx.x;
    if (i < PB * PT) {
        const float* p = data + (size_t)i * 3;
        float x0 = p[0], x1 = p[1], x2 = p[2];
        g_d2[i] = x0 * x0 + x1 * x1 + x2 * x2;
    }
    if (i < PNS * PLS) {
        int s = i / PLS, l = i % PLS;
        #pragma unroll
        for (int c = 0; c < 3; c++) {
            float v = -2.f * ker[i * 3 + c];
            __nv_bfloat16 hi = __float2bfloat16(v);
            __nv_bfloat16 lo = __float2bfloat16(v - __bfloat162float(hi));
            g_khi[s * KPAD + l * 3 + c] = __bfloat16_as_ushort(hi);
            g_klo[s * KPAD + l * 3 + c] = __bfloat16_as_ushort(lo);
        }
    }
    if (i < PB * PNS) g_amin[i] = 0xFFFFFFFFu;
    // warp-parallel k2: 32 lanes x 3 elements per shapelet
    if (i < PNS * 32) {
        int s = i >> 5, lane = i & 31;
        const float* kp = ker + s * KF + lane * 3;
        float v0 = kp[0], v1 = kp[1], v2 = kp[2];
        float k2 = v0 * v0 + v1 * v1 + v2 * v2;
        #pragma unroll
        for (int off = 16; off > 0; off >>= 1)
            k2 += __shfl_xor_sync(0xFFFFFFFFu, k2, off);
        if (lane == 0) g_k2[s] = k2;
    }
    if (i == 0) g_done = 0u;
}

// prep2: phase arrays (bf16 split inline, direct from data) + a2 from d2
__global__ void prep2_kernel(const float* __restrict__ data) {
    const int HP = PTF / 2;
    int j = blockIdx.x * blockDim.x + threadIdx.x;
    if (j < 8 * PB * HP) {
        int i2 = j % HP;
        int r  = j / HP;            // = p*PB + b
        int b  = r % PB;
        int p  = r / PB;
        int e0 = 2 * i2 + p;
        const float* db = data + (size_t)b * FLATN;
        float v0 = (e0 < FLATN)     ? db[e0]     : 0.f;
        float v1 = (e0 + 1 < FLATN) ? db[e0 + 1] : 0.f;
        u32 hi, lo; split2(v0, v1, hi, lo);
        ((u32*)g_xhi)[r * HP + i2] = hi;
        ((u32*)g_xlo)[r * HP + i2] = lo;
    }
    if (j < PB * PT) {
        int b = j / PT, w = j % PT;
        float s = 1e30f;
        if (w < PW) {
            const float* d = g_d2 + b * PT + w;
            s = 0.f;
            #pragma unroll
            for (int q = 0; q < PLS; q++) s += d[q];
        }
        g_a2[j] = s;
    }
}

// ---------------------------------------------------------------------------
// issue cp.async group for one item: 2 terms x 64 rows x 12 quads + a2
__device__ __forceinline__ void issue_item(u32 sbase, int buf, int b, int w0) {
    int tid = threadIdx.x;
    u32 bufbase = sbase + (u32)buf * BUFSZ;
    #pragma unroll
    for (int rep = 0; rep < 6; rep++) {
        int c = tid + rep * 256;            // 0..1535
        int term = c / 768;
        int cc = c - term * 768;
        int row = cc / 12, q = cc - row * 12;
        int E = 3 * (w0 + row), p = E & 7;
        const u16* src = (term ? g_xlo : g_xhi)
                         + (size_t)(p * PB + b) * PTF + (E - p) + q * 8;
        u32 dst = bufbase + (u32)term * BTERM + (u32)row * BSTR + (u32)q * 16;
        CPASYNC16(dst, src);
    }
    if (tid < NTILE) {
        const float* src = g_a2 + (size_t)b * PT + w0 + tid;
        u32 dst = sbase + SM_A2 + (u32)buf * 256 + (u32)tid * 4;
        CPASYNC4(dst, src);
    }
    asm volatile("cp.async.commit_group;" ::: "memory");
}

// ---------------------------------------------------------------------------
// Main (R8-exact loop): persistent A fragments, cp.async double-buffered B.
__global__ __launch_bounds__(THREADS, 1) void mma_main_kernel(
        float* __restrict__ out) {
    extern __shared__ __align__(16) char smem[];
    u32 sbase = smem_u32(smem);
    int tid  = threadIdx.x;
    int lane = tid & 31;
    int warp = tid >> 5;                 // 0..7 -> M rows warp*32..+31
    int g    = lane >> 2;                // 0..7
    int tg   = lane & 3;                 // 0..3

    // ---- Persistent A fragments (mma layout), loaded once via LDG
    u32 Ah[48], Al[48];                  // [ks*8 + mt*4 + q]
    {
        int r0 = warp * 32 + g;
        #pragma unroll
        for (int ks = 0; ks < 6; ks++) {
            #pragma unroll
            for (int mt = 0; mt < 2; mt++) {
                int r = r0 + mt * 16;
                int col = ks * 16 + tg * 2;
                const u16* ph = g_khi + (size_t)r * KPAD + col;
                const u16* pl = g_klo + (size_t)r * KPAD + col;
                int o = ks * 8 + mt * 4;
                Ah[o + 0] = *(const u32*)(ph);
                Ah[o + 1] = *(const u32*)(ph + 8 * KPAD);
                Ah[o + 2] = *(const u32*)(ph + 8);
                Ah[o + 3] = *(const u32*)(ph + 8 * KPAD + 8);
                Al[o + 0] = *(const u32*)(pl);
                Al[o + 1] = *(const u32*)(pl + 8 * KPAD);
                Al[o + 2] = *(const u32*)(pl + 8);
                Al[o + 3] = *(const u32*)(pl + 8 * KPAD + 8);
            }
        }
    }

    // ldmatrix B per-thread offset (proven mapping)
    int ti = lane >> 3, l8 = lane & 7;
    u32 boff = (u32)((((ti >> 1) * 8 + l8) * BSTR) + (ti & 1) * 16);

    // ---- prologue: prefetch first item into buf 0
    int item0 = blockIdx.x;
    issue_item(sbase, 0, item0 >> 7, (item0 & 127) * NTILE);

    int buf = 0;
    for (int u = item0; u < NITEMS; u += gridDim.x) {
        int b = u >> 7;
        int un = u + gridDim.x;
        if (un < NITEMS) {
            issue_item(sbase, buf ^ 1, un >> 7, (un & 127) * NTILE);
            asm volatile("cp.async.wait_group 1;" ::: "memory");
        } else {
            asm volatile("cp.async.wait_group 0;" ::: "memory");
        }
        __syncthreads();

        // ---- 3-term GEMM on buf: D = Ah*Bh + Ah*Bl + Al*Bh
        float d[2][8][4];
        #pragma unroll
        for (int mt = 0; mt < 2; mt++)
            #pragma unroll
            for (int jb = 0; jb < 8; jb++)
                #pragma unroll
                for (int q = 0; q < 4; q++) d[mt][jb][q] = 0.f;

        u32 bhbase = sbase + (u32)buf * BUFSZ + boff;
        u32 blbase = bhbase + BTERM;
        #pragma unroll
        for (int ks = 0; ks < 6; ks++) {
            u32 bh[16], bl[16];
            #pragma unroll
            for (int jp = 0; jp < 4; jp++) {
                LDSM4(bh[jp*4+0], bh[jp*4+1], bh[jp*4+2], bh[jp*4+3],
                      bhbase + jp * (16 * BSTR) + ks * 32);
                LDSM4(bl[jp*4+0], bl[jp*4+1], bl[jp*4+2], bl[jp*4+3],
                      blbase + jp * (16 * BSTR) + ks * 32);
            }
            #pragma unroll
            for (int mt = 0; mt < 2; mt++) {
                int o = ks * 8 + mt * 4;
                #pragma unroll
                for (int jp = 0; jp < 4; jp++) {
                    MMA16816(d[mt][2*jp],   Ah[o], Ah[o+1], Ah[o+2], Ah[o+3],
                             bh[jp*4+0], bh[jp*4+1]);
                    MMA16816(d[mt][2*jp+1], Ah[o], Ah[o+1], Ah[o+2], Ah[o+3],
                             bh[jp*4+2], bh[jp*4+3]);
                    MMA16816(d[mt][2*jp],   Ah[o], Ah[o+1], Ah[o+2], Ah[o+3],
                             bl[jp*4+0], bl[jp*4+1]);
                    MMA16816(d[mt][2*jp+1], Ah[o], Ah[o+1], Ah[o+2], Ah[o+3],
                             bl[jp*4+2], bl[jp*4+3]);
                    MMA16816(d[mt][2*jp],   Al[o], Al[o+1], Al[o+2], Al[o+3],
                             bh[jp*4+0], bh[jp*4+1]);
                    MMA16816(d[mt][2*jp+1], Al[o], Al[o+1], Al[o+2], Al[o+3],
                             bh[jp*4+2], bh[jp*4+3]);
                }
            }
        }

        // ---- Epilogue: +a2, min over 64 windows, atomicMin per shapelet
        const float* a2sh = (const float*)(smem + SM_A2 + buf * 256);
        #pragma unroll
        for (int mt = 0; mt < 2; mt++) {
            float m0 = 3.4e38f, m1 = 3.4e38f;
            #pragma unroll
            for (int jb = 0; jb < 8; jb++) {
                float aa0 = a2sh[jb * 8 + tg * 2];
                float aa1 = a2sh[jb * 8 + tg * 2 + 1];
                m0 = fminf(m0, fminf(d[mt][jb][0] + aa0, d[mt][jb][1] + aa1));
                m1 = fminf(m1, fminf(d[mt][jb][2] + aa0, d[mt][jb][3] + aa1));
            }
            m0 = fminf(m0, __shfl_xor_sync(0xFFFFFFFFu, m0, 1));
            m0 = fminf(m0, __shfl_xor_sync(0xFFFFFFFFu, m0, 2));
            m1 = fminf(m1, __shfl_xor_sync(0xFFFFFFFFu, m1, 1));
            m1 = fminf(m1, __shfl_xor_sync(0xFFFFFFFFu, m1, 2));
            if (tg == 0) {
                int srow = warp * 32 + mt * 16 + g;
                atomicMin(&g_amin[b * PNS + srow],     fenc(m0));
                atomicMin(&g_amin[b * PNS + srow + 8], fenc(m1));
            }
        }
        __syncthreads();    // all reads of buf done before it is refilled
        buf ^= 1;
    }

    // ---- Fused finish: last CTA to arrive writes the output
    __threadfence();
    __shared__ u32 s_rank;
    if (tid == 0) s_rank = atomicAdd(&g_done, 1u);
    __syncthreads();
    if (s_rank == gridDim.x - 1) {
        __threadfence();
        for (int i = tid; i < PB * PNS; i += THREADS) {
            u32 enc = __ldcg(&g_amin[i]);
            out[i] = (fdec(enc) + g_k2[i & (PNS - 1)]) * (1.0f / (float)PLS);
        }
    }
}

// ---------------------------------------------------------------------------
extern "C" void kernel_launch(void* const* d_in, const int* in_sizes, int n_in,
                              void* d_out, int out_size) {
    const float* data = (const float*)d_in[0];   // [32, 8192, 3]
    const float* ker  = (const float*)d_in[1];   // [256, 32, 3]
    float* out = (float*)d_out;                  // [32, 256]

    cudaFuncSetAttribute(mma_main_kernel,
                         cudaFuncAttributeMaxDynamicSharedMemorySize, SM_TOT);
    int dev = 0, nsm = 148;
    cudaGetDevice(&dev);
    cudaDeviceGetAttribute(&nsm, cudaDevAttrMultiProcessorCount, dev);
    if (nsm > NITEMS) nsm = NITEMS;

    prep1_kernel<<<(PB * PT + 255) / 256, 256>>>(data, ker);
    prep2_kernel<<<(8 * PB * (PTF / 2) + 255) / 256, 256>>>(data);

    mma_main_kernel<<<nsm, THREADS, SM_TOT>>>(out);
}

// round 12
// speedup vs baseline: 1.1729x; 1.0596x over previous
#include <cuda_runtime.h>
#include <cuda_bf16.h>

// Problem constants
#define PB   32
#define PT   8192
#define PC   3
#define PLS  32
#define PNS  256
#define PW   (PT - PLS + 1)        // 8161

#define KF      96                 // K = LS*C
#define KPAD    128                // global K row pad (u16 elements)
#define NTILE   64                 // windows per item
#define WTILES  (PT / NTILE)       // 128
#define NITEMS  (PB * WTILES)      // 4096
#define THREADS 256

#define FLATN   (PT * PC)          // 24576
#define PTF     (FLATN + 96)       // phase-array padded length (24672)

#define BSTR    208                // B row stride bytes (104 bf16, conflict-free)
#define BTERM   13312              // 64 rows * 208
#define BUFSZ   26624              // hi + lo
#define NBUF    4
#define SM_A2   (NBUF * BUFSZ)     // 106496
#define SM_TOT  (SM_A2 + NBUF * 256)  // 107520

typedef unsigned int u32;
typedef unsigned short u16;
typedef unsigned long long u64;

// Device scratch (allocations forbidden)
__device__ __align__(16) u16 g_xhi[8 * PB * PTF];   // 8 phase-shifted flat bf16 hi
__device__ __align__(16) u16 g_xlo[8 * PB * PTF];   // 8 phase-shifted flat bf16 lo
__device__ __align__(16) u16 g_khi[PNS * KPAD];     // bf16(-2k) hi
__device__ __align__(16) u16 g_klo[PNS * KPAD];     // bf16(-2k) lo
__device__ float g_d2[PB * PT];
__device__ float g_a2[PB * PT];                     // padded; >=PW poisoned
__device__ float g_k2[PNS];
__device__ u32   g_amin[PB * PNS];
__device__ u32   g_done;

// ---------------------------------------------------------------------------
__device__ __forceinline__ u32 smem_u32(const void* p) {
    u32 a; asm("{ .reg .u64 t; cvta.to.shared.u64 t, %1; cvt.u32.u64 %0, t; }"
               : "=r"(a) : "l"(p));
    return a;
}
__device__ __forceinline__ u32 fenc(float f) {
    u32 u = __float_as_uint(f);
    return (u & 0x80000000u) ? ~u : (u | 0x80000000u);
}
__device__ __forceinline__ float fdec(u32 u) {
    u32 b = (u & 0x80000000u) ? (u & 0x7FFFFFFFu) : ~u;
    return __uint_as_float(b);
}
__device__ __forceinline__ void split2(float v0, float v1, u32& hi, u32& lo) {
    __nv_bfloat16 h0 = __float2bfloat16(v0);
    __nv_bfloat16 h1 = __float2bfloat16(v1);
    __nv_bfloat16 l0 = __float2bfloat16(v0 - __bfloat162float(h0));
    __nv_bfloat16 l1 = __float2bfloat16(v1 - __bfloat162float(h1));
    hi = (u32)__bfloat16_as_ushort(h0) | ((u32)__bfloat16_as_ushort(h1) << 16);
    lo = (u32)__bfloat16_as_ushort(l0) | ((u32)__bfloat16_as_ushort(l1) << 16);
}

#define LDSM4(r0, r1, r2, r3, addr) \
    asm volatile("ldmatrix.sync.aligned.m8n8.x4.shared.b16 {%0,%1,%2,%3}, [%4];" \
        : "=r"(r0), "=r"(r1), "=r"(r2), "=r"(r3) : "r"(addr))

#define MMA16816(d, a0, a1, a2, a3, b0, b1) \
    asm volatile("mma.sync.aligned.m16n8k16.row.col.f32.bf16.bf16.f32 " \
        "{%0,%1,%2,%3}, {%4,%5,%6,%7}, {%8,%9}, {%0,%1,%2,%3};" \
        : "+f"((d)[0]), "+f"((d)[1]), "+f"((d)[2]), "+f"((d)[3]) \
        : "r"(a0), "r"(a1), "r"(a2), "r"(a3), "r"(b0), "r"(b1))

#define CPASYNC16(dst, src) \
    asm volatile("cp.async.cg.shared.global [%0], [%1], 16;" :: "r"(dst), "l"(src))
#define CPASYNC4(dst, src) \
    asm volatile("cp.async.ca.shared.global [%0], [%1], 4;" :: "r"(dst), "l"(src))

// ---------------------------------------------------------------------------
// prep1: d2, K(-2k) hi/lo, amin init, warp-parallel k2, done counter
__global__ void prep1_kernel(const float* __restrict__ data,
                             const float* __restrict__ ker) {
    int i = blockIdx.x * blockDim.x + threadIdx.x;
    if (i < PB * PT) {
        const float* p = data + (size_t)i * 3;
        float x0 = p[0], x1 = p[1], x2 = p[2];
        g_d2[i] = x0 * x0 + x1 * x1 + x2 * x2;
    }
    if (i < PNS * PLS) {
        int s = i / PLS, l = i % PLS;
        #pragma unroll
        for (int c = 0; c < 3; c++) {
            float v = -2.f * ker[i * 3 + c];
            __nv_bfloat16 hi = __float2bfloat16(v);
            __nv_bfloat16 lo = __float2bfloat16(v - __bfloat162float(hi));
            g_khi[s * KPAD + l * 3 + c] = __bfloat16_as_ushort(hi);
            g_klo[s * KPAD + l * 3 + c] = __bfloat16_as_ushort(lo);
        }
    }
    if (i < PB * PNS) g_amin[i] = 0xFFFFFFFFu;
    if (i < PNS * 32) {
        int s = i >> 5, lane = i & 31;
        const float* kp = ker + s * KF + lane * 3;
        float v0 = kp[0], v1 = kp[1], v2 = kp[2];
        float k2 = v0 * v0 + v1 * v1 + v2 * v2;
        #pragma unroll
        for (int off = 16; off > 0; off >>= 1)
            k2 += __shfl_xor_sync(0xFFFFFFFFu, k2, off);
        if (lane == 0) g_k2[s] = k2;
    }
    if (i == 0) g_done = 0u;
}

// prep2: phase arrays (bf16 split inline, direct from data) + a2 from d2
__global__ void prep2_kernel(const float* __restrict__ data) {
    const int HP = PTF / 2;
    int j = blockIdx.x * blockDim.x + threadIdx.x;
    if (j < 8 * PB * HP) {
        int i2 = j % HP;
        int r  = j / HP;            // = p*PB + b
        int b  = r % PB;
        int p  = r / PB;
        int e0 = 2 * i2 + p;
        const float* db = data + (size_t)b * FLATN;
        float v0 = (e0 < FLATN)     ? db[e0]     : 0.f;
        float v1 = (e0 + 1 < FLATN) ? db[e0 + 1] : 0.f;
        u32 hi, lo; split2(v0, v1, hi, lo);
        ((u32*)g_xhi)[r * HP + i2] = hi;
        ((u32*)g_xlo)[r * HP + i2] = lo;
    }
    if (j < PB * PT) {
        int b = j / PT, w = j % PT;
        float s = 1e30f;
        if (w < PW) {
            const float* d = g_d2 + b * PT + w;
            s = 0.f;
            #pragma unroll
            for (int q = 0; q < PLS; q++) s += d[q];
        }
        g_a2[j] = s;
    }
}

// ---------------------------------------------------------------------------
// issue cp.async group for one item: 2 terms x 64 rows x 12 quads + a2
__device__ __forceinline__ void issue_item(u32 sbase, int buf, int b, int w0) {
    int tid = threadIdx.x;
    u32 bufbase = sbase + (u32)buf * BUFSZ;
    #pragma unroll
    for (int rep = 0; rep < 6; rep++) {
        int c = tid + rep * 256;            // 0..1535
        int term = c / 768;
        int cc = c - term * 768;
        int row = cc / 12, q = cc - row * 12;
        int E = 3 * (w0 + row), p = E & 7;
        const u16* src = (term ? g_xlo : g_xhi)
                         + (size_t)(p * PB + b) * PTF + (E - p) + q * 8;
        u32 dst = bufbase + (u32)term * BTERM + (u32)row * BSTR + (u32)q * 16;
        CPASYNC16(dst, src);
    }
    if (tid < NTILE) {
        const float* src = g_a2 + (size_t)b * PT + w0 + tid;
        u32 dst = sbase + SM_A2 + (u32)buf * 256 + (u32)tid * 4;
        CPASYNC4(dst, src);
    }
    asm volatile("cp.async.commit_group;" ::: "memory");
}

// ---------------------------------------------------------------------------
// Main: contiguous item ranges, 4-buffer ring, register-deferred min.
__global__ __launch_bounds__(THREADS, 1) void mma_main_kernel(
        float* __restrict__ out) {
    extern __shared__ __align__(16) char smem[];
    u32 sbase = smem_u32(smem);
    int tid  = threadIdx.x;
    int lane = tid & 31;
    int warp = tid >> 5;                 // 0..7 -> M rows warp*32..+31
    int g    = lane >> 2;                // 0..7
    int tg   = lane & 3;                 // 0..3

    // ---- Persistent A fragments (mma layout), loaded once via LDG
    u32 Ah[48], Al[48];                  // [ks*8 + mt*4 + q]
    {
        int r0 = warp * 32 + g;
        #pragma unroll
        for (int ks = 0; ks < 6; ks++) {
            #pragma unroll
            for (int mt = 0; mt < 2; mt++) {
                int r = r0 + mt * 16;
                int col = ks * 16 + tg * 2;
                const u16* ph = g_khi + (size_t)r * KPAD + col;
                const u16* pl = g_klo + (size_t)r * KPAD + col;
                int o = ks * 8 + mt * 4;
                Ah[o + 0] = *(const u32*)(ph);
                Ah[o + 1] = *(const u32*)(ph + 8 * KPAD);
                Ah[o + 2] = *(const u32*)(ph + 8);
                Ah[o + 3] = *(const u32*)(ph + 8 * KPAD + 8);
                Al[o + 0] = *(const u32*)(pl);
                Al[o + 1] = *(const u32*)(pl + 8 * KPAD);
                Al[o + 2] = *(const u32*)(pl + 8);
                Al[o + 3] = *(const u32*)(pl + 8 * KPAD + 8);
            }
        }
    }

    // ldmatrix B per-thread offset (proven mapping)
    int ti = lane >> 3, l8 = lane & 7;
    u32 boff = (u32)((((ti >> 1) * 8 + l8) * BSTR) + (ti & 1) * 16);

    // ---- contiguous item range for this CTA
    int G    = gridDim.x;
    int base = NITEMS / G, rem = NITEMS % G;
    int cta  = blockIdx.x;
    int lo   = cta * base + (cta < rem ? cta : rem);
    int cnt  = base + (cta < rem ? 1 : 0);

    // ---- prologue: prefetch up to 2 items
    if (cnt > 0) issue_item(sbase, 0, lo >> 7,        (lo & 127) * NTILE);
    if (cnt > 1) issue_item(sbase, 1, (lo + 1) >> 7, ((lo + 1) & 127) * NTILE);

    float mm[2][2];
    mm[0][0] = mm[0][1] = mm[1][0] = mm[1][1] = 3.4e38f;

    for (int k = 0; k < cnt; k++) {
        int u  = lo + k;
        int b  = u >> 7;
        int bf = k & (NBUF - 1);

        if (k + 2 < cnt) {
            int un = u + 2;
            issue_item(sbase, (k + 2) & (NBUF - 1), un >> 7, (un & 127) * NTILE);
            asm volatile("cp.async.wait_group 2;" ::: "memory");
        } else if (k + 1 < cnt) {
            asm volatile("cp.async.wait_group 1;" ::: "memory");
        } else {
            asm volatile("cp.async.wait_group 0;" ::: "memory");
        }
        __syncthreads();   // single barrier per item (see 4-buffer safety note)

        // ---- 3-term GEMM on buf: D = Ah*Bh + Ah*Bl + Al*Bh  (R8-exact)
        float d[2][8][4];
        #pragma unroll
        for (int mt = 0; mt < 2; mt++)
            #pragma unroll
            for (int jb = 0; jb < 8; jb++)
                #pragma unroll
                for (int q = 0; q < 4; q++) d[mt][jb][q] = 0.f;

        u32 bhbase = sbase + (u32)bf * BUFSZ + boff;
        u32 blbase = bhbase + BTERM;
        #pragma unroll
        for (int ks = 0; ks < 6; ks++) {
            u32 bh[16], bl[16];
            #pragma unroll
            for (int jp = 0; jp < 4; jp++) {
                LDSM4(bh[jp*4+0], bh[jp*4+1], bh[jp*4+2], bh[jp*4+3],
                      bhbase + jp * (16 * BSTR) + ks * 32);
                LDSM4(bl[jp*4+0], bl[jp*4+1], bl[jp*4+2], bl[jp*4+3],
                      blbase + jp * (16 * BSTR) + ks * 32);
            }
            #pragma unroll
            for (int mt = 0; mt < 2; mt++) {
                int o = ks * 8 + mt * 4;
                #pragma unroll
                for (int jp = 0; jp < 4; jp++) {
                    MMA16816(d[mt][2*jp],   Ah[o], Ah[o+1], Ah[o+2], Ah[o+3],
                             bh[jp*4+0], bh[jp*4+1]);
                    MMA16816(d[mt][2*jp+1], Ah[o], Ah[o+1], Ah[o+2], Ah[o+3],
                             bh[jp*4+2], bh[jp*4+3]);
                    MMA16816(d[mt][2*jp],   Ah[o], Ah[o+1], Ah[o+2], Ah[o+3],
                             bl[jp*4+0], bl[jp*4+1]);
                    MMA16816(d[mt][2*jp+1], Ah[o], Ah[o+1], Ah[o+2], Ah[o+3],
                             bl[jp*4+2], bl[jp*4+3]);
                    MMA16816(d[mt][2*jp],   Al[o], Al[o+1], Al[o+2], Al[o+3],
                             bh[jp*4+0], bh[jp*4+1]);
                    MMA16816(d[mt][2*jp+1], Al[o], Al[o+1], Al[o+2], Al[o+3],
                             bh[jp*4+2], bh[jp*4+3]);
                }
            }
        }

        // ---- accumulate running min in registers (+a2)
        const float* a2sh = (const float*)(smem + SM_A2 + bf * 256);
        #pragma unroll
        for (int mt = 0; mt < 2; mt++) {
            float m0 = mm[mt][0], m1 = mm[mt][1];
            #pragma unroll
            for (int jb = 0; jb < 8; jb++) {
                float aa0 = a2sh[jb * 8 + tg * 2];
                float aa1 = a2sh[jb * 8 + tg * 2 + 1];
                m0 = fminf(m0, fminf(d[mt][jb][0] + aa0, d[mt][jb][1] + aa1));
                m1 = fminf(m1, fminf(d[mt][jb][2] + aa0, d[mt][jb][3] + aa1));
            }
            mm[mt][0] = m0; mm[mt][1] = m1;
        }

        // ---- flush at batch boundary or range end
        bool fl = (k == cnt - 1) || (((u + 1) >> 7) != b);
        if (fl) {
            #pragma unroll
            for (int mt = 0; mt < 2; mt++) {
                float m0 = mm[mt][0], m1 = mm[mt][1];
                m0 = fminf(m0, __shfl_xor_sync(0xFFFFFFFFu, m0, 1));
                m0 = fminf(m0, __shfl_xor_sync(0xFFFFFFFFu, m0, 2));
                m1 = fminf(m1, __shfl_xor_sync(0xFFFFFFFFu, m1, 1));
                m1 = fminf(m1, __shfl_xor_sync(0xFFFFFFFFu, m1, 2));
                if (tg == 0) {
                    int srow = warp * 32 + mt * 16 + g;
                    atomicMin(&g_amin[b * PNS + srow],     fenc(m0));
                    atomicMin(&g_amin[b * PNS + srow + 8], fenc(m1));
                }
                mm[mt][0] = 3.4e38f; mm[mt][1] = 3.4e38f;
            }
        }
    }

    // ---- Fused finish: last CTA to arrive writes the output
    __threadfence();
    __shared__ u32 s_rank;
    if (tid == 0) s_rank = atomicAdd(&g_done, 1u);
    __syncthreads();
    if (s_rank == gridDim.x - 1) {
        __threadfence();
        for (int i = tid; i < PB * PNS; i += THREADS) {
            u32 enc = __ldcg(&g_amin[i]);
            out[i] = (fdec(enc) + g_k2[i & (PNS - 1)]) * (1.0f / (float)PLS);
        }
    }
}

// ---------------------------------------------------------------------------
extern "C" void kernel_launch(void* const* d_in, const int* in_sizes, int n_in,
                              void* d_out, int out_size) {
    const float* data = (const float*)d_in[0];   // [32, 8192, 3]
    const float* ker  = (const float*)d_in[1];   // [256, 32, 3]
    float* out = (float*)d_out;                  // [32, 256]

    cudaFuncSetAttribute(mma_main_kernel,
                         cudaFuncAttributeMaxDynamicSharedMemorySize, SM_TOT);
    int dev = 0, nsm = 148;
    cudaGetDevice(&dev);
    cudaDeviceGetAttribute(&nsm, cudaDevAttrMultiProcessorCount, dev);
    if (nsm > NITEMS) nsm = NITEMS;

    prep1_kernel<<<(PB * PT + 255) / 256, 256>>>(data, ker);
    prep2_kernel<<<(8 * PB * (PTF / 2) + 255) / 256, 256>>>(data);

    mma_main_kernel<<<nsm, THREADS, SM_TOT>>>(out);
}